// round 6
// baseline (speedup 1.0000x reference)
#include <cuda_runtime.h>
#include <cuda_bf16.h>
#include <math.h>
#include <stdint.h>

// Problem constants
#define TOTAL  32768
#define D      1280
#define NSEG   128
#define DHEAD  512

// GEMM tiling
#define TILE_M   128
#define TILE_N   256
#define KCH      64                 // K elements per chunk (128B bf16 row)
#define NT_TILES (D / TILE_N)       // 5
#define MT_TILES (TOTAL / TILE_M)   // 256
#define KCHUNKS  (D / KCH)          // 20
#define ATILE_B  (TILE_M * 128)     // 16384
#define BTILE_B  (TILE_N * 128)     // 32768
#define STAGE_B  (2 * ATILE_B + 2 * BTILE_B)   // 98304
#define NSTAGES  2
#define DSMEM    (NSTAGES * STAGE_B + 1024)

// ---------------- scratch (static device globals; no allocation) -----------
__device__ float g_s[TOTAL];
__device__ float g_spart[NT_TILES * TOTAL];
__device__ float g_att[TOTAL];
__device__ int   g_start[NSEG + 1];
__device__ float g_pooled[NSEG * D];
__device__ float g_W1t[D * DHEAD];
__device__ __align__(1024) unsigned char g_Fhi[(size_t)TOTAL * D * 2];
__device__ __align__(1024) unsigned char g_Flo[(size_t)TOTAL * D * 2];
__device__ __align__(1024) unsigned char g_Whi[(size_t)D * D * 2];
__device__ __align__(1024) unsigned char g_Wlo[(size_t)D * D * 2];

// ---------------------------- PTX helpers ----------------------------------
__device__ __forceinline__ uint32_t smem_u32(const void* p) {
    uint32_t a;
    asm("{ .reg .u64 t; cvta.to.shared.u64 t, %1; cvt.u32.u64 %0, t; }"
        : "=r"(a) : "l"(p));
    return a;
}
__device__ __forceinline__ uint32_t swz128(uint32_t b) {
    return b ^ ((b >> 3) & 0x70);
}

#define MBARRIER_INIT(addr, cnt) \
    asm volatile("mbarrier.init.shared.b64 [%0], %1;" :: "r"(addr), "r"(cnt) : "memory")
#define MBARRIER_EXPECT_TX(addr, bytes) \
    asm volatile("mbarrier.arrive.expect_tx.shared.b64 _, [%0], %1;" :: "r"(addr), "r"(bytes) : "memory")
#define MBARRIER_ARRIVE(addr) \
    asm volatile("mbarrier.arrive.release.cta.shared.b64 _, [%0];" :: "r"(addr) : "memory")
#define MBARRIER_WAIT_PARITY(addr, par) do {                                   \
    uint32_t _m = (addr); uint32_t _p = (par); uint32_t _d;                    \
    asm volatile("{\n\t.reg .pred p;\n\t"                                      \
        "mbarrier.try_wait.parity.acquire.cta.shared::cta.b64 p, [%1], %2;\n\t"\
        "selp.b32 %0, 1, 0, p;\n\t}" : "=r"(_d) : "r"(_m), "r"(_p) : "memory");\
    if (!_d) {                                                                 \
        asm volatile("{\n\t.reg .pred P1;\n\t"                                 \
        "WL_%=:\n\t"                                                           \
        "mbarrier.try_wait.parity.acquire.cta.shared::cta.b64 P1, [%0], %1, 0x989680;\n\t"\
        "@P1 bra.uni WD_%=;\n\t"                                               \
        "bra.uni WL_%=;\n\t"                                                   \
        "WD_%=:\n\t}" :: "r"(_m), "r"(_p) : "memory");                         \
    }                                                                          \
} while (0)

__device__ __forceinline__ void bulk_cp(uint32_t dst, const void* src,
                                        uint32_t bytes, uint32_t mbar) {
    asm volatile(
        "cp.async.bulk.shared::cluster.global.mbarrier::complete_tx::bytes [%0], [%1], %2, [%3];"
        :: "r"(dst), "l"(src), "r"(bytes), "r"(mbar) : "memory");
}

#define LDSM4(r, addr) \
    asm volatile("ldmatrix.sync.aligned.m8n8.x4.shared.b16 {%0,%1,%2,%3}, [%4];" \
        : "=r"((r)[0]), "=r"((r)[1]), "=r"((r)[2]), "=r"((r)[3]) : "r"(addr))

#define MMA16816(c, a, b0, b1) \
    asm volatile("mma.sync.aligned.m16n8k16.row.col.f32.bf16.bf16.f32 " \
        "{%0,%1,%2,%3}, {%4,%5,%6,%7}, {%8,%9}, {%0,%1,%2,%3};" \
        : "+f"((c)[0]), "+f"((c)[1]), "+f"((c)[2]), "+f"((c)[3]) \
        : "r"((a)[0]), "r"((a)[1]), "r"((a)[2]), "r"((a)[3]), "r"(b0), "r"(b1))

// ---------------------------------------------------------------------------
__global__ void bounds_kernel(const int* __restrict__ ids) {
    int i = blockIdx.x * blockDim.x + threadIdx.x;
    if (i < TOTAL) {
        if (i == 0) { g_start[ids[0]] = 0; g_start[NSEG] = TOTAL; }
        else if (ids[i] != ids[i - 1]) g_start[ids[i]] = i;
    }
}

__global__ void transpose_w1_kernel(const float* __restrict__ W1) {
    int idx = blockIdx.x * blockDim.x + threadIdx.x;
    if (idx < DHEAD * D) {
        int n = idx / D, k = idx - n * D;
        g_W1t[k * DHEAD + n] = W1[idx];
    }
}

// ---------------------------------------------------------------------------
__device__ __forceinline__ void split8(const float* x, uint4& hi, uint4& lo) {
    uint32_t h[4], l[4];
#pragma unroll
    for (int j = 0; j < 4; ++j) {
        float a = x[2 * j], b = x[2 * j + 1];
        __nv_bfloat162 hp = __floats2bfloat162_rn(a, b);
        float la = a - __bfloat162float(__low2bfloat16(hp));
        float lb = b - __bfloat162float(__high2bfloat16(hp));
        __nv_bfloat162 lp = __floats2bfloat162_rn(la, lb);
        h[j] = *(uint32_t*)&hp;
        l[j] = *(uint32_t*)&lp;
    }
    hi = make_uint4(h[0], h[1], h[2], h[3]);
    lo = make_uint4(l[0], l[1], l[2], l[3]);
}

__global__ void convF_kernel(const float* __restrict__ F) {
    int idx = blockIdx.x * blockDim.x + threadIdx.x;
    if (idx >= TOTAL * (D / 8)) return;
    int row = idx / (D / 8), cg = idx - row * (D / 8);
    int mt = row >> 7, r = row & 127;
    int kc = cg >> 3, gi = cg & 7;
    float x[8];
    const float4* src = (const float4*)(F + (size_t)row * D + cg * 8);
    float4 x0 = src[0], x1 = src[1];
    x[0]=x0.x; x[1]=x0.y; x[2]=x0.z; x[3]=x0.w; x[4]=x1.x; x[5]=x1.y; x[6]=x1.z; x[7]=x1.w;
    uint4 hi, lo; split8(x, hi, lo);
    size_t base = (size_t)(mt * KCHUNKS + kc) * ATILE_B;
    uint32_t off = swz128((uint32_t)(r * 128 + gi * 16));
    *(uint4*)(g_Fhi + base + off) = hi;
    *(uint4*)(g_Flo + base + off) = lo;
}

// B tiles now 256 rows (TILE_N=256)
__global__ void convW_kernel(const float* __restrict__ W) {
    int idx = blockIdx.x * blockDim.x + threadIdx.x;
    if (idx >= D * (D / 8)) return;
    int row = idx / (D / 8), cg = idx - row * (D / 8);
    int nt = row >> 8, r = row & 255;
    int kc = cg >> 3, gi = cg & 7;
    float x[8];
    const float4* src = (const float4*)(W + (size_t)row * D + cg * 8);
    float4 x0 = src[0], x1 = src[1];
    x[0]=x0.x; x[1]=x0.y; x[2]=x0.z; x[3]=x0.w; x[4]=x1.x; x[5]=x1.y; x[6]=x1.z; x[7]=x1.w;
    uint4 hi, lo; split8(x, hi, lo);
    size_t base = (size_t)(nt * KCHUNKS + kc) * BTILE_B;
    uint32_t off = swz128((uint32_t)(r * 128 + gi * 16));
    *(uint4*)(g_Whi + base + off) = hi;
    *(uint4*)(g_Wlo + base + off) = lo;
}

// ---------------------------------------------------------------------------
// K1: mma.sync bf16 split GEMM + tanh/dot-v epilogue.
// grid = 256 mt x 5 nt. 8 warps (2m x 4n), warp tile 64x64.
// 3 passes sequenced to cap register liveness; mbarrier full/empty flow.
// ---------------------------------------------------------------------------
__global__ void __launch_bounds__(256, 1)
gemm_tc_kernel(const float* __restrict__ bw, const float* __restrict__ v) {
    extern __shared__ __align__(16) char smem_raw[];
    __shared__ __align__(8) unsigned long long full_mb[NSTAGES];
    __shared__ __align__(8) unsigned long long empty_mb[NSTAGES];
    __shared__ float red[4][TILE_M];

    const uint32_t TILES = (smem_u32(smem_raw) + 1023) & ~1023u;
    const uint32_t FB = smem_u32(&full_mb[0]);
    const uint32_t EB = smem_u32(&empty_mb[0]);

    const int tid = threadIdx.x, wid = tid >> 5, lane = tid & 31;
    const int mt = blockIdx.x / NT_TILES, nt = blockIdx.x % NT_TILES;
    const int wm = wid >> 2, wn = wid & 3;   // 2 m-warps x 4 n-warps

    if (tid == 0) {
#pragma unroll
        for (int s = 0; s < NSTAGES; ++s) {
            MBARRIER_INIT(FB + s * 8, 1);
            MBARRIER_INIT(EB + s * 8, 256);
        }
    }
    __syncthreads();

    const unsigned char* aHi = g_Fhi + (size_t)mt * KCHUNKS * ATILE_B;
    const unsigned char* aLo = g_Flo + (size_t)mt * KCHUNKS * ATILE_B;
    const unsigned char* bHi = g_Whi + (size_t)nt * KCHUNKS * BTILE_B;
    const unsigned char* bLo = g_Wlo + (size_t)nt * KCHUNKS * BTILE_B;

    if (tid == 0) {
        // prefill stage 0 (chunk 0)
        uint32_t st = TILES;
        MBARRIER_EXPECT_TX(FB, (uint32_t)STAGE_B);
        bulk_cp(st,               aHi, ATILE_B, FB);
        bulk_cp(st + ATILE_B,     aLo, ATILE_B, FB);
        bulk_cp(st + 2 * ATILE_B, bHi, BTILE_B, FB);
        bulk_cp(st + 2 * ATILE_B + BTILE_B, bLo, BTILE_B, FB);
    }

    // ldmatrix address components (within tile, swizzled)
    const uint32_t xm = (lane & 7) << 4;
    const uint32_t a_rb = (uint32_t)(wm * 64 + (lane & 15)) * 128;
    const uint32_t a_cb = (uint32_t)((lane >> 4) * 16);
    const uint32_t b_rb = (uint32_t)(wn * 64 + (lane & 7) + ((lane >> 4) & 1) * 8) * 128;
    const uint32_t b_cb = (uint32_t)(((lane >> 3) & 1) * 16);

    float acc[4][8][4];
#pragma unroll
    for (int t = 0; t < 4; ++t)
#pragma unroll
        for (int j = 0; j < 8; ++j)
#pragma unroll
            for (int e = 0; e < 4; ++e) acc[t][j][e] = 0.f;

    for (int k = 0; k < KCHUNKS; ++k) {
        const int s = k % NSTAGES;
        MBARRIER_WAIT_PARITY(FB + s * 8, (uint32_t)((k / NSTAGES) & 1));

        // producer: refill next stage (chunk kn = k+1)
        if (tid == 0 && k + NSTAGES - 1 < KCHUNKS) {
            const int kn = k + NSTAGES - 1;
            const int s2 = kn % NSTAGES;
            if (kn >= NSTAGES)
                MBARRIER_WAIT_PARITY(EB + s2 * 8, (uint32_t)((kn / NSTAGES - 1) & 1));
            uint32_t st2 = TILES + s2 * STAGE_B;
            MBARRIER_EXPECT_TX(FB + s2 * 8, (uint32_t)STAGE_B);
            bulk_cp(st2,               aHi + (size_t)kn * ATILE_B, ATILE_B, FB + s2 * 8);
            bulk_cp(st2 + ATILE_B,     aLo + (size_t)kn * ATILE_B, ATILE_B, FB + s2 * 8);
            bulk_cp(st2 + 2 * ATILE_B, bHi + (size_t)kn * BTILE_B, BTILE_B, FB + s2 * 8);
            bulk_cp(st2 + 2 * ATILE_B + BTILE_B, bLo + (size_t)kn * BTILE_B, BTILE_B, FB + s2 * 8);
        }

        const uint32_t st = TILES + s * STAGE_B;
        const uint32_t stB = st + 2 * ATILE_B;
#pragma unroll
        for (int q = 0; q < 4; ++q) {
            uint32_t Ah[4][4], Al[4][4], Bh[4][4], Bl[4][4];
            const uint32_t qa = (q * 32 + a_cb) ^ xm;
            const uint32_t qb = (q * 32 + b_cb) ^ xm;
#pragma unroll
            for (int t = 0; t < 4; ++t)
                LDSM4(Ah[t], st + a_rb + t * 2048 + qa);
#pragma unroll
            for (int g = 0; g < 4; ++g)
                LDSM4(Bh[g], stB + b_rb + g * 2048 + qb);
            // pass 1: Ah * Bh
#pragma unroll
            for (int t = 0; t < 4; ++t)
#pragma unroll
                for (int g = 0; g < 4; ++g)
#pragma unroll
                    for (int h = 0; h < 2; ++h)
                        MMA16816(acc[t][g * 2 + h], Ah[t], Bh[g][h * 2], Bh[g][h * 2 + 1]);
            // pass 2: Ah * Bl
#pragma unroll
            for (int g = 0; g < 4; ++g)
                LDSM4(Bl[g], stB + BTILE_B + b_rb + g * 2048 + qb);
#pragma unroll
            for (int t = 0; t < 4; ++t)
#pragma unroll
                for (int g = 0; g < 4; ++g)
#pragma unroll
                    for (int h = 0; h < 2; ++h)
                        MMA16816(acc[t][g * 2 + h], Ah[t], Bl[g][h * 2], Bl[g][h * 2 + 1]);
            // pass 3: Al * Bh
#pragma unroll
            for (int t = 0; t < 4; ++t)
                LDSM4(Al[t], st + ATILE_B + a_rb + t * 2048 + qa);
#pragma unroll
            for (int t = 0; t < 4; ++t)
#pragma unroll
                for (int g = 0; g < 4; ++g)
#pragma unroll
                    for (int h = 0; h < 2; ++h)
                        MMA16816(acc[t][g * 2 + h], Al[t], Bh[g][h * 2], Bh[g][h * 2 + 1]);
        }
        MBARRIER_ARRIVE(EB + s * 8);
    }

    // epilogue: srow[r] = sum_n tanh(acc + bw[n]) * v[n]
#pragma unroll
    for (int t = 0; t < 4; ++t) {
        float s0 = 0.f, s1 = 0.f;
#pragma unroll
        for (int j = 0; j < 8; ++j) {
            int n0 = nt * TILE_N + wn * 64 + j * 8 + (lane & 3) * 2;
            float bw0 = __ldg(&bw[n0]),     v0 = __ldg(&v[n0]);
            float bw1 = __ldg(&bw[n0 + 1]), v1 = __ldg(&v[n0 + 1]);
            s0 += tanhf(acc[t][j][0] + bw0) * v0 + tanhf(acc[t][j][1] + bw1) * v1;
            s1 += tanhf(acc[t][j][2] + bw0) * v0 + tanhf(acc[t][j][3] + bw1) * v1;
        }
        s0 += __shfl_xor_sync(0xFFFFFFFFu, s0, 1);
        s0 += __shfl_xor_sync(0xFFFFFFFFu, s0, 2);
        s1 += __shfl_xor_sync(0xFFFFFFFFu, s1, 1);
        s1 += __shfl_xor_sync(0xFFFFFFFFu, s1, 2);
        if ((lane & 3) == 0) {
            int r = wm * 64 + t * 16 + (lane >> 2);
            red[wn][r] = s0;
            red[wn][r + 8] = s1;
        }
    }
    __syncthreads();
    if (tid < TILE_M)
        g_spart[nt * TOTAL + mt * TILE_M + tid] =
            (red[0][tid] + red[1][tid]) + (red[2][tid] + red[3][tid]);
}

// K1b: reduce s partials across the 5 N-tiles
__global__ void sreduce_kernel() {
    int i = blockIdx.x * blockDim.x + threadIdx.x;
    if (i < TOTAL) {
        float t = 0.f;
#pragma unroll
        for (int nt = 0; nt < NT_TILES; ++nt) t += g_spart[nt * TOTAL + i];
        g_s[i] = t;
    }
}

// ---------------------------------------------------------------------------
__global__ void softmax_kernel() {
    __shared__ float sm[256];
    const int b = blockIdx.x, tid = threadIdx.x;
    const int s0 = g_start[b], s1 = g_start[b + 1];
    float m = -1e30f;
    for (int i = s0 + tid; i < s1; i += 256) m = fmaxf(m, g_s[i]);
    sm[tid] = m; __syncthreads();
    for (int st = 128; st >= 1; st >>= 1) {
        if (tid < st) sm[tid] = fmaxf(sm[tid], sm[tid + st]);
        __syncthreads();
    }
    m = sm[0]; __syncthreads();
    float z = 0.f;
    for (int i = s0 + tid; i < s1; i += 256) z += expf(g_s[i] - m);
    sm[tid] = z; __syncthreads();
    for (int st = 128; st >= 1; st >>= 1) {
        if (tid < st) sm[tid] += sm[tid + st];
        __syncthreads();
    }
    float inv = 1.f / sm[0];
    for (int i = s0 + tid; i < s1; i += 256)
        g_att[i] = expf(g_s[i] - m) * inv;
}

// ---------------------------------------------------------------------------
__global__ void pool_kernel(const float* __restrict__ F) {
    const int seg = blockIdx.y;
    const int col = blockIdx.x * 128 + threadIdx.x;
    const int s0 = g_start[seg], s1 = g_start[seg + 1];
    float acc = 0.f;
    int i = s0;
    for (; i + 3 < s1; i += 4) {
        float a0 = g_att[i], a1 = g_att[i + 1], a2 = g_att[i + 2], a3 = g_att[i + 3];
        float f0 = F[(size_t)(i + 0) * D + col];
        float f1 = F[(size_t)(i + 1) * D + col];
        float f2 = F[(size_t)(i + 2) * D + col];
        float f3 = F[(size_t)(i + 3) * D + col];
        acc = fmaf(a0, f0, acc); acc = fmaf(a1, f1, acc);
        acc = fmaf(a2, f2, acc); acc = fmaf(a3, f3, acc);
    }
    for (; i < s1; ++i) acc = fmaf(g_att[i], F[(size_t)i * D + col], acc);
    g_pooled[seg * D + col] = acc;
}

// ---------------------------------------------------------------------------
__global__ void __launch_bounds__(DHEAD)
head_kernel(const float* __restrict__ b1, const float* __restrict__ W2,
            const float* __restrict__ b2, float* __restrict__ out) {
    __shared__ float p[D];
    __shared__ float red[DHEAD];
    const int seg = blockIdx.x, t = threadIdx.x;
    for (int k = t; k < D; k += DHEAD) p[k] = g_pooled[seg * D + k];
    __syncthreads();
    float acc = 0.f;
#pragma unroll 8
    for (int k = 0; k < D; ++k) acc = fmaf(p[k], g_W1t[k * DHEAD + t], acc);
    float h = fmaxf(acc + b1[t], 0.f);
    red[t] = h * W2[t];
    __syncthreads();
    for (int st = DHEAD / 2; st >= 1; st >>= 1) {
        if (t < st) red[t] += red[t + st];
        __syncthreads();
    }
    if (t == 0) out[seg] = red[0] + b2[0];
}

// ---------------------------------------------------------------------------
extern "C" void kernel_launch(void* const* d_in, const int* in_sizes, int n_in,
                              void* d_out, int out_size) {
    const float* features = (const float*)d_in[0];
    const float* Ww       = (const float*)d_in[1];
    const float* bw       = (const float*)d_in[2];
    const float* v        = (const float*)d_in[3];
    const float* W1       = (const float*)d_in[4];
    const float* b1       = (const float*)d_in[5];
    const float* W2       = (const float*)d_in[6];
    const float* b2       = (const float*)d_in[7];
    const int*   seg_ids  = (const int*)d_in[8];
    float* out = (float*)d_out;

    cudaFuncSetAttribute(gemm_tc_kernel,
                         cudaFuncAttributeMaxDynamicSharedMemorySize, DSMEM);

    // Order chosen so the GEMM lands in the ncu capture slot (4th launch).
    convF_kernel<<<(TOTAL * (D / 8) + 511) / 512, 512>>>(features);
    convW_kernel<<<(D * (D / 8) + 511) / 512, 512>>>(Ww);
    bounds_kernel<<<TOTAL / 256, 256>>>(seg_ids);
    gemm_tc_kernel<<<MT_TILES * NT_TILES, 256, DSMEM>>>(bw, v);
    transpose_w1_kernel<<<(DHEAD * D + 511) / 512, 512>>>(W1);
    sreduce_kernel<<<TOTAL / 256, 256>>>();
    softmax_kernel<<<NSEG, 256>>>();
    pool_kernel<<<dim3(D / 128, NSEG), 128>>>(features);
    head_kernel<<<NSEG, DHEAD>>>(b1, W2, b2, out);
}

// round 7
// speedup vs baseline: 1.3128x; 1.3128x over previous
#include <cuda_runtime.h>
#include <cuda_fp16.h>
#include <math.h>
#include <stdint.h>

// Problem constants
#define TOTAL  32768
#define D      1280
#define NSEG   128
#define DHEAD  512

// GEMM tiling
#define TILE_M   128
#define TILE_N   256
#define KCH      64                 // K elements per chunk (128B fp16 row)
#define NT_TILES (D / TILE_N)       // 5
#define MT_TILES (TOTAL / TILE_M)   // 256
#define KCHUNKS  (D / KCH)          // 20
#define ATILE_B  (TILE_M * 128)     // 16384
#define BTILE_B  (TILE_N * 128)     // 32768
#define STAGE_B  (2 * ATILE_B + BTILE_B)   // 65536: Ah + Al + Bh
#define NSTAGES  2
#define DSMEM    (NSTAGES * STAGE_B + 1024)

// ---------------- scratch (static device globals; no allocation) -----------
__device__ float g_s[TOTAL];
__device__ float g_spart[NT_TILES * TOTAL];
__device__ float g_att[TOTAL];
__device__ int   g_start[NSEG + 1];
__device__ float g_pooled[NSEG * D];
__device__ float g_W1t[D * DHEAD];
// fp16 operands, tile-contiguous + SW128 pre-swizzled
__device__ __align__(1024) unsigned char g_Fh[(size_t)TOTAL * D * 2];
__device__ __align__(1024) unsigned char g_Fl[(size_t)TOTAL * D * 2];
__device__ __align__(1024) unsigned char g_Wh[(size_t)D * D * 2];

// ---------------------------- PTX helpers ----------------------------------
__device__ __forceinline__ uint32_t smem_u32(const void* p) {
    uint32_t a;
    asm("{ .reg .u64 t; cvta.to.shared.u64 t, %1; cvt.u32.u64 %0, t; }"
        : "=r"(a) : "l"(p));
    return a;
}
__device__ __forceinline__ uint32_t swz128(uint32_t b) {
    return b ^ ((b >> 3) & 0x70);
}

#define MBARRIER_INIT(addr, cnt) \
    asm volatile("mbarrier.init.shared.b64 [%0], %1;" :: "r"(addr), "r"(cnt) : "memory")
#define MBARRIER_EXPECT_TX(addr, bytes) \
    asm volatile("mbarrier.arrive.expect_tx.shared.b64 _, [%0], %1;" :: "r"(addr), "r"(bytes) : "memory")
#define MBARRIER_ARRIVE(addr) \
    asm volatile("mbarrier.arrive.release.cta.shared.b64 _, [%0];" :: "r"(addr) : "memory")
#define MBARRIER_WAIT_PARITY(addr, par) do {                                   \
    uint32_t _m = (addr); uint32_t _p = (par); uint32_t _d;                    \
    asm volatile("{\n\t.reg .pred p;\n\t"                                      \
        "mbarrier.try_wait.parity.acquire.cta.shared::cta.b64 p, [%1], %2;\n\t"\
        "selp.b32 %0, 1, 0, p;\n\t}" : "=r"(_d) : "r"(_m), "r"(_p) : "memory");\
    if (!_d) {                                                                 \
        asm volatile("{\n\t.reg .pred P1;\n\t"                                 \
        "WL_%=:\n\t"                                                           \
        "mbarrier.try_wait.parity.acquire.cta.shared::cta.b64 P1, [%0], %1, 0x989680;\n\t"\
        "@P1 bra.uni WD_%=;\n\t"                                               \
        "bra.uni WL_%=;\n\t"                                                   \
        "WD_%=:\n\t}" :: "r"(_m), "r"(_p) : "memory");                         \
    }                                                                          \
} while (0)

__device__ __forceinline__ void bulk_cp(uint32_t dst, const void* src,
                                        uint32_t bytes, uint32_t mbar) {
    asm volatile(
        "cp.async.bulk.shared::cluster.global.mbarrier::complete_tx::bytes [%0], [%1], %2, [%3];"
        :: "r"(dst), "l"(src), "r"(bytes), "r"(mbar) : "memory");
}

#define LDSM4(r, addr) \
    asm volatile("ldmatrix.sync.aligned.m8n8.x4.shared.b16 {%0,%1,%2,%3}, [%4];" \
        : "=r"((r)[0]), "=r"((r)[1]), "=r"((r)[2]), "=r"((r)[3]) : "r"(addr))

#define MMA16816(c, a, b0, b1) \
    asm volatile("mma.sync.aligned.m16n8k16.row.col.f32.f16.f16.f32 " \
        "{%0,%1,%2,%3}, {%4,%5,%6,%7}, {%8,%9}, {%0,%1,%2,%3};" \
        : "+f"((c)[0]), "+f"((c)[1]), "+f"((c)[2]), "+f"((c)[3]) \
        : "r"((a)[0]), "r"((a)[1]), "r"((a)[2]), "r"((a)[3]), "r"(b0), "r"(b1))

// ---------------------------------------------------------------------------
__global__ void bounds_kernel(const int* __restrict__ ids) {
    int i = blockIdx.x * blockDim.x + threadIdx.x;
    if (i < TOTAL) {
        if (i == 0) { g_start[ids[0]] = 0; g_start[NSEG] = TOTAL; }
        else if (ids[i] != ids[i - 1]) g_start[ids[i]] = i;
    }
}

__global__ void transpose_w1_kernel(const float* __restrict__ W1) {
    int idx = blockIdx.x * blockDim.x + threadIdx.x;
    if (idx < DHEAD * D) {
        int n = idx / D, k = idx - n * D;
        g_W1t[k * DHEAD + n] = W1[idx];
    }
}

// ---------------------------------------------------------------------------
// fp16 hi/lo split: 8 fp32 -> 8 hi-fp16 (16B) + 8 lo-fp16 (residual)
// ---------------------------------------------------------------------------
__device__ __forceinline__ void split8h(const float* x, uint4& hi, uint4& lo) {
    uint32_t h[4], l[4];
#pragma unroll
    for (int j = 0; j < 4; ++j) {
        float a = x[2 * j], b = x[2 * j + 1];
        __half2 hp = __floats2half2_rn(a, b);
        float la = a - __half2float(__low2half(hp));
        float lb = b - __half2float(__high2half(hp));
        __half2 lp = __floats2half2_rn(la, lb);
        h[j] = *(uint32_t*)&hp;
        l[j] = *(uint32_t*)&lp;
    }
    hi = make_uint4(h[0], h[1], h[2], h[3]);
    lo = make_uint4(l[0], l[1], l[2], l[3]);
}

__global__ void convF_kernel(const float* __restrict__ F) {
    int idx = blockIdx.x * blockDim.x + threadIdx.x;
    if (idx >= TOTAL * (D / 8)) return;
    int row = idx / (D / 8), cg = idx - row * (D / 8);
    int mt = row >> 7, r = row & 127;
    int kc = cg >> 3, gi = cg & 7;
    float x[8];
    const float4* src = (const float4*)(F + (size_t)row * D + cg * 8);
    float4 x0 = src[0], x1 = src[1];
    x[0]=x0.x; x[1]=x0.y; x[2]=x0.z; x[3]=x0.w; x[4]=x1.x; x[5]=x1.y; x[6]=x1.z; x[7]=x1.w;
    uint4 hi, lo; split8h(x, hi, lo);
    size_t base = (size_t)(mt * KCHUNKS + kc) * ATILE_B;
    uint32_t off = swz128((uint32_t)(r * 128 + gi * 16));
    *(uint4*)(g_Fh + base + off) = hi;
    *(uint4*)(g_Fl + base + off) = lo;
}

// W -> fp16 hi only; tiles of 256 rows (TILE_N)
__global__ void convW_kernel(const float* __restrict__ W) {
    int idx = blockIdx.x * blockDim.x + threadIdx.x;
    if (idx >= D * (D / 8)) return;
    int row = idx / (D / 8), cg = idx - row * (D / 8);
    int nt = row >> 8, r = row & 255;
    int kc = cg >> 3, gi = cg & 7;
    const float4* src = (const float4*)(W + (size_t)row * D + cg * 8);
    float4 x0 = src[0], x1 = src[1];
    uint32_t h[4];
    __half2 p0 = __floats2half2_rn(x0.x, x0.y); h[0] = *(uint32_t*)&p0;
    __half2 p1 = __floats2half2_rn(x0.z, x0.w); h[1] = *(uint32_t*)&p1;
    __half2 p2 = __floats2half2_rn(x1.x, x1.y); h[2] = *(uint32_t*)&p2;
    __half2 p3 = __floats2half2_rn(x1.z, x1.w); h[3] = *(uint32_t*)&p3;
    size_t base = (size_t)(nt * KCHUNKS + kc) * BTILE_B;
    uint32_t off = swz128((uint32_t)(r * 128 + gi * 16));
    *(uint4*)(g_Wh + base + off) = make_uint4(h[0], h[1], h[2], h[3]);
}

// ---------------------------------------------------------------------------
// K1: 2-pass fp16 split GEMM (Ah*Bh + Al*Bh) + tanh/dot-v epilogue.
// grid = 256 mt x 5 nt. 8 warps (2m x 4n), warp tile 64x64.
// ---------------------------------------------------------------------------
__global__ void __launch_bounds__(256, 1)
gemm_tc_kernel(const float* __restrict__ bw, const float* __restrict__ v) {
    extern __shared__ __align__(16) char smem_raw[];
    __shared__ __align__(8) unsigned long long full_mb[NSTAGES];
    __shared__ __align__(8) unsigned long long empty_mb[NSTAGES];
    __shared__ float red[4][TILE_M];

    const uint32_t TILES = (smem_u32(smem_raw) + 1023) & ~1023u;
    const uint32_t FB = smem_u32(&full_mb[0]);
    const uint32_t EB = smem_u32(&empty_mb[0]);

    const int tid = threadIdx.x, wid = tid >> 5, lane = tid & 31;
    const int mt = blockIdx.x / NT_TILES, nt = blockIdx.x % NT_TILES;
    const int wm = wid >> 2, wn = wid & 3;   // 2 m-warps x 4 n-warps

    if (tid == 0) {
#pragma unroll
        for (int s = 0; s < NSTAGES; ++s) {
            MBARRIER_INIT(FB + s * 8, 1);
            MBARRIER_INIT(EB + s * 8, 256);
        }
    }
    __syncthreads();

    const unsigned char* aHi = g_Fh + (size_t)mt * KCHUNKS * ATILE_B;
    const unsigned char* aLo = g_Fl + (size_t)mt * KCHUNKS * ATILE_B;
    const unsigned char* bHi = g_Wh + (size_t)nt * KCHUNKS * BTILE_B;

    if (tid == 0) {
        uint32_t st = TILES;
        MBARRIER_EXPECT_TX(FB, (uint32_t)STAGE_B);
        bulk_cp(st,               aHi, ATILE_B, FB);
        bulk_cp(st + ATILE_B,     aLo, ATILE_B, FB);
        bulk_cp(st + 2 * ATILE_B, bHi, BTILE_B, FB);
    }

    // ldmatrix address components (within tile, swizzled)
    const uint32_t xm = (lane & 7) << 4;
    const uint32_t a_rb = (uint32_t)(wm * 64 + (lane & 15)) * 128;
    const uint32_t a_cb = (uint32_t)((lane >> 4) * 16);
    const uint32_t b_rb = (uint32_t)(wn * 64 + (lane & 7) + ((lane >> 4) & 1) * 8) * 128;
    const uint32_t b_cb = (uint32_t)(((lane >> 3) & 1) * 16);

    float acc[4][8][4];
#pragma unroll
    for (int t = 0; t < 4; ++t)
#pragma unroll
        for (int j = 0; j < 8; ++j)
#pragma unroll
            for (int e = 0; e < 4; ++e) acc[t][j][e] = 0.f;

    for (int k = 0; k < KCHUNKS; ++k) {
        const int s = k % NSTAGES;
        MBARRIER_WAIT_PARITY(FB + s * 8, (uint32_t)((k / NSTAGES) & 1));

        // producer: refill next stage
        if (tid == 0 && k + NSTAGES - 1 < KCHUNKS) {
            const int kn = k + NSTAGES - 1;
            const int s2 = kn % NSTAGES;
            if (kn >= NSTAGES)
                MBARRIER_WAIT_PARITY(EB + s2 * 8, (uint32_t)((kn / NSTAGES - 1) & 1));
            uint32_t st2 = TILES + s2 * STAGE_B;
            MBARRIER_EXPECT_TX(FB + s2 * 8, (uint32_t)STAGE_B);
            bulk_cp(st2,               aHi + (size_t)kn * ATILE_B, ATILE_B, FB + s2 * 8);
            bulk_cp(st2 + ATILE_B,     aLo + (size_t)kn * ATILE_B, ATILE_B, FB + s2 * 8);
            bulk_cp(st2 + 2 * ATILE_B, bHi + (size_t)kn * BTILE_B, BTILE_B, FB + s2 * 8);
        }

        const uint32_t st = TILES + s * STAGE_B;
        const uint32_t stB = st + 2 * ATILE_B;
#pragma unroll
        for (int q = 0; q < 4; ++q) {
            uint32_t Ah[4][4], Al[4][4], Bh[4][4];
            const uint32_t qa = (q * 32 + a_cb) ^ xm;
            const uint32_t qb = (q * 32 + b_cb) ^ xm;
#pragma unroll
            for (int t = 0; t < 4; ++t)
                LDSM4(Ah[t], st + a_rb + t * 2048 + qa);
#pragma unroll
            for (int g = 0; g < 4; ++g)
                LDSM4(Bh[g], stB + b_rb + g * 2048 + qb);
            // pass 1: Ah * Bh
#pragma unroll
            for (int t = 0; t < 4; ++t)
#pragma unroll
                for (int g = 0; g < 4; ++g)
#pragma unroll
                    for (int h = 0; h < 2; ++h)
                        MMA16816(acc[t][g * 2 + h], Ah[t], Bh[g][h * 2], Bh[g][h * 2 + 1]);
            // pass 2: Al * Bh
#pragma unroll
            for (int t = 0; t < 4; ++t)
                LDSM4(Al[t], st + ATILE_B + a_rb + t * 2048 + qa);
#pragma unroll
            for (int t = 0; t < 4; ++t)
#pragma unroll
                for (int g = 0; g < 4; ++g)
#pragma unroll
                    for (int h = 0; h < 2; ++h)
                        MMA16816(acc[t][g * 2 + h], Al[t], Bh[g][h * 2], Bh[g][h * 2 + 1]);
        }
        MBARRIER_ARRIVE(EB + s * 8);
    }

    // epilogue: srow[r] = sum_n tanh(acc + bw[n]) * v[n]
#pragma unroll
    for (int t = 0; t < 4; ++t) {
        float s0 = 0.f, s1 = 0.f;
#pragma unroll
        for (int j = 0; j < 8; ++j) {
            int n0 = nt * TILE_N + wn * 64 + j * 8 + (lane & 3) * 2;
            float bw0 = __ldg(&bw[n0]),     v0 = __ldg(&v[n0]);
            float bw1 = __ldg(&bw[n0 + 1]), v1 = __ldg(&v[n0 + 1]);
            s0 += tanhf(acc[t][j][0] + bw0) * v0 + tanhf(acc[t][j][1] + bw1) * v1;
            s1 += tanhf(acc[t][j][2] + bw0) * v0 + tanhf(acc[t][j][3] + bw1) * v1;
        }
        s0 += __shfl_xor_sync(0xFFFFFFFFu, s0, 1);
        s0 += __shfl_xor_sync(0xFFFFFFFFu, s0, 2);
        s1 += __shfl_xor_sync(0xFFFFFFFFu, s1, 1);
        s1 += __shfl_xor_sync(0xFFFFFFFFu, s1, 2);
        if ((lane & 3) == 0) {
            int r = wm * 64 + t * 16 + (lane >> 2);
            red[wn][r] = s0;
            red[wn][r + 8] = s1;
        }
    }
    __syncthreads();
    if (tid < TILE_M)
        g_spart[nt * TOTAL + mt * TILE_M + tid] =
            (red[0][tid] + red[1][tid]) + (red[2][tid] + red[3][tid]);
}

// ---------------------------------------------------------------------------
// K2: per-segment stable softmax (folds the 5-way partial reduction inline)
// ---------------------------------------------------------------------------
__global__ void softmax_kernel() {
    __shared__ float sm[256];
    const int b = blockIdx.x, tid = threadIdx.x;
    const int s0 = g_start[b], s1 = g_start[b + 1];
    float m = -1e30f;
    for (int i = s0 + tid; i < s1; i += 256) {
        float t = 0.f;
#pragma unroll
        for (int nt = 0; nt < NT_TILES; ++nt) t += g_spart[nt * TOTAL + i];
        g_s[i] = t;
        m = fmaxf(m, t);
    }
    sm[tid] = m; __syncthreads();
    for (int st = 128; st >= 1; st >>= 1) {
        if (tid < st) sm[tid] = fmaxf(sm[tid], sm[tid + st]);
        __syncthreads();
    }
    m = sm[0]; __syncthreads();
    float z = 0.f;
    for (int i = s0 + tid; i < s1; i += 256) z += expf(g_s[i] - m);
    sm[tid] = z; __syncthreads();
    for (int st = 128; st >= 1; st >>= 1) {
        if (tid < st) sm[tid] += sm[tid + st];
        __syncthreads();
    }
    float inv = 1.f / sm[0];
    for (int i = s0 + tid; i < s1; i += 256)
        g_att[i] = expf(g_s[i] - m) * inv;
}

// ---------------------------------------------------------------------------
__global__ void pool_kernel(const float* __restrict__ F) {
    const int seg = blockIdx.y;
    const int col = blockIdx.x * 128 + threadIdx.x;
    const int s0 = g_start[seg], s1 = g_start[seg + 1];
    float acc = 0.f;
    int i = s0;
    for (; i + 3 < s1; i += 4) {
        float a0 = g_att[i], a1 = g_att[i + 1], a2 = g_att[i + 2], a3 = g_att[i + 3];
        float f0 = F[(size_t)(i + 0) * D + col];
        float f1 = F[(size_t)(i + 1) * D + col];
        float f2 = F[(size_t)(i + 2) * D + col];
        float f3 = F[(size_t)(i + 3) * D + col];
        acc = fmaf(a0, f0, acc); acc = fmaf(a1, f1, acc);
        acc = fmaf(a2, f2, acc); acc = fmaf(a3, f3, acc);
    }
    for (; i < s1; ++i) acc = fmaf(g_att[i], F[(size_t)i * D + col], acc);
    g_pooled[seg * D + col] = acc;
}

// ---------------------------------------------------------------------------
__global__ void __launch_bounds__(DHEAD)
head_kernel(const float* __restrict__ b1, const float* __restrict__ W2,
            const float* __restrict__ b2, float* __restrict__ out) {
    __shared__ float p[D];
    __shared__ float red[DHEAD];
    const int seg = blockIdx.x, t = threadIdx.x;
    for (int k = t; k < D; k += DHEAD) p[k] = g_pooled[seg * D + k];
    __syncthreads();
    float acc = 0.f;
#pragma unroll 8
    for (int k = 0; k < D; ++k) acc = fmaf(p[k], g_W1t[k * DHEAD + t], acc);
    float h = fmaxf(acc + b1[t], 0.f);
    red[t] = h * W2[t];
    __syncthreads();
    for (int st = DHEAD / 2; st >= 1; st >>= 1) {
        if (t < st) red[t] += red[t + st];
        __syncthreads();
    }
    if (t == 0) out[seg] = red[0] + b2[0];
}

// ---------------------------------------------------------------------------
extern "C" void kernel_launch(void* const* d_in, const int* in_sizes, int n_in,
                              void* d_out, int out_size) {
    const float* features = (const float*)d_in[0];
    const float* Ww       = (const float*)d_in[1];
    const float* bw       = (const float*)d_in[2];
    const float* v        = (const float*)d_in[3];
    const float* W1       = (const float*)d_in[4];
    const float* b1       = (const float*)d_in[5];
    const float* W2       = (const float*)d_in[6];
    const float* b2       = (const float*)d_in[7];
    const int*   seg_ids  = (const int*)d_in[8];
    float* out = (float*)d_out;

    cudaFuncSetAttribute(gemm_tc_kernel,
                         cudaFuncAttributeMaxDynamicSharedMemorySize, DSMEM);

    // GEMM is the 4th launch (ncu capture slot).
    convF_kernel<<<(TOTAL * (D / 8) + 511) / 512, 512>>>(features);
    convW_kernel<<<(D * (D / 8) + 511) / 512, 512>>>(Ww);
    bounds_kernel<<<TOTAL / 256, 256>>>(seg_ids);
    gemm_tc_kernel<<<MT_TILES * NT_TILES, 256, DSMEM>>>(bw, v);
    transpose_w1_kernel<<<(DHEAD * D + 511) / 512, 512>>>(W1);
    softmax_kernel<<<NSEG, 256>>>();
    pool_kernel<<<dim3(D / 128, NSEG), 128>>>(features);
    head_kernel<<<NSEG, DHEAD>>>(b1, W2, b2, out);
}

// round 8
// speedup vs baseline: 1.9174x; 1.4605x over previous
#include <cuda_runtime.h>
#include <cuda_fp16.h>
#include <math.h>
#include <stdint.h>

// Problem constants
#define TOTAL  32768
#define D      1280
#define NSEG   128
#define DHEAD  512

// GEMM tiling
#define TILE_M   128
#define TILE_N   256
#define KCH      64                 // K elements per chunk (128B fp16 row)
#define NT_TILES (D / TILE_N)       // 5
#define MT_TILES (TOTAL / TILE_M)   // 256
#define KCHUNKS  (D / KCH)          // 20
#define ATILE_B  (TILE_M * 128)     // 16384
#define BTILE_B  (TILE_N * 128)     // 32768
#define STAGE_B  (ATILE_B + BTILE_B)   // 49152: Ah + Bh
#define NSTAGES  4
#define DSMEM    (NSTAGES * STAGE_B + 1024)

// ---------------- scratch (static device globals; no allocation) -----------
__device__ float g_s[TOTAL];
__device__ float g_spart[NT_TILES * TOTAL];
__device__ float g_att[TOTAL];
__device__ int   g_start[NSEG + 1];
__device__ float g_pooled[NSEG * D];
__device__ float g_W1t[D * DHEAD];
// fp16 operands, tile-contiguous + SW128 pre-swizzled
__device__ __align__(1024) unsigned char g_Fh[(size_t)TOTAL * D * 2];
__device__ __align__(1024) unsigned char g_Wh[(size_t)D * D * 2];

// ---------------------------- PTX helpers ----------------------------------
__device__ __forceinline__ uint32_t smem_u32(const void* p) {
    uint32_t a;
    asm("{ .reg .u64 t; cvta.to.shared.u64 t, %1; cvt.u32.u64 %0, t; }"
        : "=r"(a) : "l"(p));
    return a;
}
__device__ __forceinline__ uint32_t swz128(uint32_t b) {
    return b ^ ((b >> 3) & 0x70);
}

#define MBARRIER_INIT(addr, cnt) \
    asm volatile("mbarrier.init.shared.b64 [%0], %1;" :: "r"(addr), "r"(cnt) : "memory")
#define MBARRIER_EXPECT_TX(addr, bytes) \
    asm volatile("mbarrier.arrive.expect_tx.shared.b64 _, [%0], %1;" :: "r"(addr), "r"(bytes) : "memory")
#define MBARRIER_ARRIVE(addr) \
    asm volatile("mbarrier.arrive.release.cta.shared.b64 _, [%0];" :: "r"(addr) : "memory")
#define MBARRIER_WAIT_PARITY(addr, par) do {                                   \
    uint32_t _m = (addr); uint32_t _p = (par); uint32_t _d;                    \
    asm volatile("{\n\t.reg .pred p;\n\t"                                      \
        "mbarrier.try_wait.parity.acquire.cta.shared::cta.b64 p, [%1], %2;\n\t"\
        "selp.b32 %0, 1, 0, p;\n\t}" : "=r"(_d) : "r"(_m), "r"(_p) : "memory");\
    if (!_d) {                                                                 \
        asm volatile("{\n\t.reg .pred P1;\n\t"                                 \
        "WL_%=:\n\t"                                                           \
        "mbarrier.try_wait.parity.acquire.cta.shared::cta.b64 P1, [%0], %1, 0x989680;\n\t"\
        "@P1 bra.uni WD_%=;\n\t"                                               \
        "bra.uni WL_%=;\n\t"                                                   \
        "WD_%=:\n\t}" :: "r"(_m), "r"(_p) : "memory");                         \
    }                                                                          \
} while (0)

__device__ __forceinline__ void bulk_cp(uint32_t dst, const void* src,
                                        uint32_t bytes, uint32_t mbar) {
    asm volatile(
        "cp.async.bulk.shared::cluster.global.mbarrier::complete_tx::bytes [%0], [%1], %2, [%3];"
        :: "r"(dst), "l"(src), "r"(bytes), "r"(mbar) : "memory");
}

#define LDSM4(r, addr) \
    asm volatile("ldmatrix.sync.aligned.m8n8.x4.shared.b16 {%0,%1,%2,%3}, [%4];" \
        : "=r"((r)[0]), "=r"((r)[1]), "=r"((r)[2]), "=r"((r)[3]) : "r"(addr))

#define MMA16816(c, a, b0, b1) \
    asm volatile("mma.sync.aligned.m16n8k16.row.col.f32.f16.f16.f32 " \
        "{%0,%1,%2,%3}, {%4,%5,%6,%7}, {%8,%9}, {%0,%1,%2,%3};" \
        : "+f"((c)[0]), "+f"((c)[1]), "+f"((c)[2]), "+f"((c)[3]) \
        : "r"((a)[0]), "r"((a)[1]), "r"((a)[2]), "r"((a)[3]), "r"(b0), "r"(b1))

// ---------------------------------------------------------------------------
__global__ void bounds_kernel(const int* __restrict__ ids) {
    int i = blockIdx.x * blockDim.x + threadIdx.x;
    if (i < TOTAL) {
        if (i == 0) { g_start[ids[0]] = 0; g_start[NSEG] = TOTAL; }
        else if (ids[i] != ids[i - 1]) g_start[ids[i]] = i;
    }
}

__global__ void transpose_w1_kernel(const float* __restrict__ W1) {
    int idx = blockIdx.x * blockDim.x + threadIdx.x;
    if (idx < DHEAD * D) {
        int n = idx / D, k = idx - n * D;
        g_W1t[k * DHEAD + n] = W1[idx];
    }
}

// ---------------------------------------------------------------------------
// conv: fp32 -> fp16 (round to nearest), tile-contiguous SW128 swizzled
// ---------------------------------------------------------------------------
__device__ __forceinline__ uint4 pack8h(float4 x0, float4 x1) {
    uint32_t h[4];
    __half2 p0 = __floats2half2_rn(x0.x, x0.y); h[0] = *(uint32_t*)&p0;
    __half2 p1 = __floats2half2_rn(x0.z, x0.w); h[1] = *(uint32_t*)&p1;
    __half2 p2 = __floats2half2_rn(x1.x, x1.y); h[2] = *(uint32_t*)&p2;
    __half2 p3 = __floats2half2_rn(x1.z, x1.w); h[3] = *(uint32_t*)&p3;
    return make_uint4(h[0], h[1], h[2], h[3]);
}

__global__ void convF_kernel(const float* __restrict__ F) {
    int idx = blockIdx.x * blockDim.x + threadIdx.x;
    if (idx >= TOTAL * (D / 8)) return;
    int row = idx / (D / 8), cg = idx - row * (D / 8);
    int mt = row >> 7, r = row & 127;
    int kc = cg >> 3, gi = cg & 7;
    const float4* src = (const float4*)(F + (size_t)row * D + cg * 8);
    uint4 hi = pack8h(src[0], src[1]);
    size_t base = (size_t)(mt * KCHUNKS + kc) * ATILE_B;
    uint32_t off = swz128((uint32_t)(r * 128 + gi * 16));
    *(uint4*)(g_Fh + base + off) = hi;
}

// W tiles of 256 rows (TILE_N)
__global__ void convW_kernel(const float* __restrict__ W) {
    int idx = blockIdx.x * blockDim.x + threadIdx.x;
    if (idx >= D * (D / 8)) return;
    int row = idx / (D / 8), cg = idx - row * (D / 8);
    int nt = row >> 8, r = row & 255;
    int kc = cg >> 3, gi = cg & 7;
    const float4* src = (const float4*)(W + (size_t)row * D + cg * 8);
    uint4 hi = pack8h(src[0], src[1]);
    size_t base = (size_t)(nt * KCHUNKS + kc) * BTILE_B;
    uint32_t off = swz128((uint32_t)(r * 128 + gi * 16));
    *(uint4*)(g_Wh + base + off) = hi;
}

// ---------------------------------------------------------------------------
// K1: single-pass fp16 GEMM + tanh/dot-v epilogue.
// grid = 256 mt x 5 nt. 8 warps (2m x 4n), warp tile 64x64. 4-stage pipeline.
// ---------------------------------------------------------------------------
__global__ void __launch_bounds__(256, 1)
gemm_tc_kernel(const float* __restrict__ bw, const float* __restrict__ v) {
    extern __shared__ __align__(16) char smem_raw[];
    __shared__ __align__(8) unsigned long long full_mb[NSTAGES];
    __shared__ __align__(8) unsigned long long empty_mb[NSTAGES];
    __shared__ float red[4][TILE_M];

    const uint32_t TILES = (smem_u32(smem_raw) + 1023) & ~1023u;
    const uint32_t FB = smem_u32(&full_mb[0]);
    const uint32_t EB = smem_u32(&empty_mb[0]);

    const int tid = threadIdx.x, wid = tid >> 5, lane = tid & 31;
    const int mt = blockIdx.x / NT_TILES, nt = blockIdx.x % NT_TILES;
    const int wm = wid >> 2, wn = wid & 3;   // 2 m-warps x 4 n-warps

    if (tid == 0) {
#pragma unroll
        for (int s = 0; s < NSTAGES; ++s) {
            MBARRIER_INIT(FB + s * 8, 1);
            MBARRIER_INIT(EB + s * 8, 256);
        }
    }
    __syncthreads();

    const unsigned char* aHi = g_Fh + (size_t)mt * KCHUNKS * ATILE_B;
    const unsigned char* bHi = g_Wh + (size_t)nt * KCHUNKS * BTILE_B;

    if (tid == 0) {
#pragma unroll
        for (int k = 0; k < NSTAGES - 1; ++k) {
            uint32_t st = TILES + k * STAGE_B;
            MBARRIER_EXPECT_TX(FB + k * 8, (uint32_t)STAGE_B);
            bulk_cp(st,           aHi + (size_t)k * ATILE_B, ATILE_B, FB + k * 8);
            bulk_cp(st + ATILE_B, bHi + (size_t)k * BTILE_B, BTILE_B, FB + k * 8);
        }
    }

    // ldmatrix address components (within tile, swizzled)
    const uint32_t xm = (lane & 7) << 4;
    const uint32_t a_rb = (uint32_t)(wm * 64 + (lane & 15)) * 128;
    const uint32_t a_cb = (uint32_t)((lane >> 4) * 16);
    const uint32_t b_rb = (uint32_t)(wn * 64 + (lane & 7) + ((lane >> 4) & 1) * 8) * 128;
    const uint32_t b_cb = (uint32_t)(((lane >> 3) & 1) * 16);

    float acc[4][8][4];
#pragma unroll
    for (int t = 0; t < 4; ++t)
#pragma unroll
        for (int j = 0; j < 8; ++j)
#pragma unroll
            for (int e = 0; e < 4; ++e) acc[t][j][e] = 0.f;

    for (int k = 0; k < KCHUNKS; ++k) {
        const int s = k % NSTAGES;
        MBARRIER_WAIT_PARITY(FB + s * 8, (uint32_t)((k / NSTAGES) & 1));

        // producer: refill stage for chunk kn = k + NSTAGES-1
        if (tid == 0 && k + NSTAGES - 1 < KCHUNKS) {
            const int kn = k + NSTAGES - 1;
            const int s2 = kn % NSTAGES;
            if (kn >= NSTAGES)
                MBARRIER_WAIT_PARITY(EB + s2 * 8, (uint32_t)((kn / NSTAGES - 1) & 1));
            uint32_t st2 = TILES + s2 * STAGE_B;
            MBARRIER_EXPECT_TX(FB + s2 * 8, (uint32_t)STAGE_B);
            bulk_cp(st2,           aHi + (size_t)kn * ATILE_B, ATILE_B, FB + s2 * 8);
            bulk_cp(st2 + ATILE_B, bHi + (size_t)kn * BTILE_B, BTILE_B, FB + s2 * 8);
        }

        const uint32_t st = TILES + s * STAGE_B;
        const uint32_t stB = st + ATILE_B;
#pragma unroll
        for (int q = 0; q < 4; ++q) {
            uint32_t Ah[4][4], Bh[4][4];
            const uint32_t qa = (q * 32 + a_cb) ^ xm;
            const uint32_t qb = (q * 32 + b_cb) ^ xm;
#pragma unroll
            for (int t = 0; t < 4; ++t)
                LDSM4(Ah[t], st + a_rb + t * 2048 + qa);
#pragma unroll
            for (int g = 0; g < 4; ++g)
                LDSM4(Bh[g], stB + b_rb + g * 2048 + qb);
#pragma unroll
            for (int t = 0; t < 4; ++t)
#pragma unroll
                for (int g = 0; g < 4; ++g)
#pragma unroll
                    for (int h = 0; h < 2; ++h)
                        MMA16816(acc[t][g * 2 + h], Ah[t], Bh[g][h * 2], Bh[g][h * 2 + 1]);
        }
        MBARRIER_ARRIVE(EB + s * 8);
    }

    // epilogue: srow[r] = sum_n tanh(acc + bw[n]) * v[n]
#pragma unroll
    for (int t = 0; t < 4; ++t) {
        float s0 = 0.f, s1 = 0.f;
#pragma unroll
        for (int j = 0; j < 8; ++j) {
            int n0 = nt * TILE_N + wn * 64 + j * 8 + (lane & 3) * 2;
            float bw0 = __ldg(&bw[n0]),     v0 = __ldg(&v[n0]);
            float bw1 = __ldg(&bw[n0 + 1]), v1 = __ldg(&v[n0 + 1]);
            s0 += tanhf(acc[t][j][0] + bw0) * v0 + tanhf(acc[t][j][1] + bw1) * v1;
            s1 += tanhf(acc[t][j][2] + bw0) * v0 + tanhf(acc[t][j][3] + bw1) * v1;
        }
        s0 += __shfl_xor_sync(0xFFFFFFFFu, s0, 1);
        s0 += __shfl_xor_sync(0xFFFFFFFFu, s0, 2);
        s1 += __shfl_xor_sync(0xFFFFFFFFu, s1, 1);
        s1 += __shfl_xor_sync(0xFFFFFFFFu, s1, 2);
        if ((lane & 3) == 0) {
            int r = wm * 64 + t * 16 + (lane >> 2);
            red[wn][r] = s0;
            red[wn][r + 8] = s1;
        }
    }
    __syncthreads();
    if (tid < TILE_M)
        g_spart[nt * TOTAL + mt * TILE_M + tid] =
            (red[0][tid] + red[1][tid]) + (red[2][tid] + red[3][tid]);
}

// ---------------------------------------------------------------------------
// K2: per-segment stable softmax (folds the 5-way partial reduction inline)
// ---------------------------------------------------------------------------
__global__ void softmax_kernel() {
    __shared__ float sm[256];
    const int b = blockIdx.x, tid = threadIdx.x;
    const int s0 = g_start[b], s1 = g_start[b + 1];
    float m = -1e30f;
    for (int i = s0 + tid; i < s1; i += 256) {
        float t = 0.f;
#pragma unroll
        for (int nt = 0; nt < NT_TILES; ++nt) t += g_spart[nt * TOTAL + i];
        g_s[i] = t;
        m = fmaxf(m, t);
    }
    sm[tid] = m; __syncthreads();
    for (int st = 128; st >= 1; st >>= 1) {
        if (tid < st) sm[tid] = fmaxf(sm[tid], sm[tid + st]);
        __syncthreads();
    }
    m = sm[0]; __syncthreads();
    float z = 0.f;
    for (int i = s0 + tid; i < s1; i += 256) z += expf(g_s[i] - m);
    sm[tid] = z; __syncthreads();
    for (int st = 128; st >= 1; st >>= 1) {
        if (tid < st) sm[tid] += sm[tid + st];
        __syncthreads();
    }
    float inv = 1.f / sm[0];
    for (int i = s0 + tid; i < s1; i += 256)
        g_att[i] = expf(g_s[i] - m) * inv;
}

// ---------------------------------------------------------------------------
__global__ void pool_kernel(const float* __restrict__ F) {
    const int seg = blockIdx.y;
    const int col = blockIdx.x * 128 + threadIdx.x;
    const int s0 = g_start[seg], s1 = g_start[seg + 1];
    float acc = 0.f;
    int i = s0;
    for (; i + 3 < s1; i += 4) {
        float a0 = g_att[i], a1 = g_att[i + 1], a2 = g_att[i + 2], a3 = g_att[i + 3];
        float f0 = F[(size_t)(i + 0) * D + col];
        float f1 = F[(size_t)(i + 1) * D + col];
        float f2 = F[(size_t)(i + 2) * D + col];
        float f3 = F[(size_t)(i + 3) * D + col];
        acc = fmaf(a0, f0, acc); acc = fmaf(a1, f1, acc);
        acc = fmaf(a2, f2, acc); acc = fmaf(a3, f3, acc);
    }
    for (; i < s1; ++i) acc = fmaf(g_att[i], F[(size_t)i * D + col], acc);
    g_pooled[seg * D + col] = acc;
}

// ---------------------------------------------------------------------------
__global__ void __launch_bounds__(DHEAD)
head_kernel(const float* __restrict__ b1, const float* __restrict__ W2,
            const float* __restrict__ b2, float* __restrict__ out) {
    __shared__ float p[D];
    __shared__ float red[DHEAD];
    const int seg = blockIdx.x, t = threadIdx.x;
    for (int k = t; k < D; k += DHEAD) p[k] = g_pooled[seg * D + k];
    __syncthreads();
    float acc = 0.f;
#pragma unroll 8
    for (int k = 0; k < D; ++k) acc = fmaf(p[k], g_W1t[k * DHEAD + t], acc);
    float h = fmaxf(acc + b1[t], 0.f);
    red[t] = h * W2[t];
    __syncthreads();
    for (int st = DHEAD / 2; st >= 1; st >>= 1) {
        if (t < st) red[t] += red[t + st];
        __syncthreads();
    }
    if (t == 0) out[seg] = red[0] + b2[0];
}

// ---------------------------------------------------------------------------
extern "C" void kernel_launch(void* const* d_in, const int* in_sizes, int n_in,
                              void* d_out, int out_size) {
    const float* features = (const float*)d_in[0];
    const float* Ww       = (const float*)d_in[1];
    const float* bw       = (const float*)d_in[2];
    const float* v        = (const float*)d_in[3];
    const float* W1       = (const float*)d_in[4];
    const float* b1       = (const float*)d_in[5];
    const float* W2       = (const float*)d_in[6];
    const float* b2       = (const float*)d_in[7];
    const int*   seg_ids  = (const int*)d_in[8];
    float* out = (float*)d_out;

    cudaFuncSetAttribute(gemm_tc_kernel,
                         cudaFuncAttributeMaxDynamicSharedMemorySize, DSMEM);

    // GEMM is the 4th launch (ncu capture slot).
    convF_kernel<<<(TOTAL * (D / 8) + 511) / 512, 512>>>(features);
    convW_kernel<<<(D * (D / 8) + 511) / 512, 512>>>(Ww);
    bounds_kernel<<<TOTAL / 256, 256>>>(seg_ids);
    gemm_tc_kernel<<<MT_TILES * NT_TILES, 256, DSMEM>>>(bw, v);
    transpose_w1_kernel<<<(DHEAD * D + 511) / 512, 512>>>(W1);
    softmax_kernel<<<NSEG, 256>>>();
    pool_kernel<<<dim3(D / 128, NSEG), 128>>>(features);
    head_kernel<<<NSEG, DHEAD>>>(b1, W2, b2, out);
}